// round 14
// baseline (speedup 1.0000x reference)
#include <cuda_runtime.h>
#include <math.h>

#define BATCH 2048
#define NMEAS 128
#define MDIM  256
#define LNUM  10

typedef unsigned long long ull;

__device__ __forceinline__ ull pk2(float x, float y) {
    ull r; asm("mov.b64 %0, {%1, %2};" : "=l"(r) : "f"(x), "f"(y)); return r;
}
__device__ __forceinline__ float2 upk2(ull v) {
    float2 t; asm("mov.b64 {%0, %1}, %2;" : "=f"(t.x), "=f"(t.y) : "l"(v)); return t;
}
__device__ __forceinline__ void fma2(ull& d, ull a, ull b) {
    asm("fma.rn.f32x2 %0, %1, %2, %3;" : "=l"(d) : "l"(a), "l"(b), "l"(d));
}

// ---------------- scratch ----------------
__device__ float g_AAr[MDIM*MDIM], g_AAi[MDIM*MDIM];
__device__ float g_D[MDIM];
__device__ float g_AYr[BATCH*MDIM], g_AYi[BATCH*MDIM];
__device__ float g_AYtr[MDIM*BATCH], g_AYti[MDIM*BATCH];
__device__ float g_F1[32*MDIM*BATCH];
__device__ float g_fmp[2*64*BATCH];
__device__ float g_c[BATCH*9], g_d[BATCH*9], g_T[BATCH*10];
__device__ float g_Ur[BATCH*MDIM], g_Ui[BATCH*MDIM];
__device__ float g_Wr[BATCH*MDIM], g_Wi[BATCH*MDIM];
__device__ float g_Lam[BATCH*MDIM];
__device__ float g_eps2[BATCH], g_Yn[BATCH];
__device__ unsigned int g_max;

extern __shared__ float sm2[];

// ---------------- K0: fused prep (AA,D) + AY + ||Y||^2 ---------------------
__global__ void k_front(const float* __restrict__ Yr, const float* __restrict__ Yi,
                        const float* __restrict__ Ar, const float* __restrict__ Ai) {
    if (blockIdx.x < 256) {
        int i = blockIdx.x, j = threadIdx.x;
        __shared__ float cr[NMEAS], ci[NMEAS];
        if (j < NMEAS) { cr[j] = Ar[j*MDIM + i]; ci[j] = Ai[j*MDIM + i]; }
        __syncthreads();
        float sr = 0.f, si = 0.f;
        for (int n = 0; n < NMEAS; n++) {
            float arj = Ar[n*MDIM + j], aij = Ai[n*MDIM + j];
            sr += cr[n]*arj + ci[n]*aij;
            si += cr[n]*aij - ci[n]*arj;
        }
        g_AAr[i*MDIM + j] = sr;
        g_AAi[i*MDIM + j] = si;
        if (j == i) g_D[i] = sr;
        if (i == 0 && j == 0) g_max = 0u;
    } else {
        int b0 = (blockIdx.x - 256) * 8;
        int tid = threadIdx.x;
        __shared__ float sYr[8][NMEAS], sYi[8][NMEAS];
        for (int idx = tid; idx < 8*NMEAS; idx += 256) {
            int bl = idx >> 7, n = idx & 127;
            sYr[bl][n] = Yr[(b0 + bl)*NMEAS + n];
            sYi[bl][n] = Yi[(b0 + bl)*NMEAS + n];
        }
        __syncthreads();
        int m = tid;
        float ayr[8], ayi[8];
        #pragma unroll
        for (int q = 0; q < 8; q++) { ayr[q] = 0.f; ayi[q] = 0.f; }
        for (int n = 0; n < NMEAS; n++) {
            float ar = Ar[n*MDIM + m], ai = Ai[n*MDIM + m];
            #pragma unroll
            for (int q = 0; q < 8; q++) {
                float yr = sYr[q][n], yi = sYi[q][n];
                ayr[q] += ar*yr + ai*yi;
                ayi[q] += ar*yi - ai*yr;
            }
        }
        #pragma unroll
        for (int q = 0; q < 8; q++) {
            g_AYr[(b0 + q)*MDIM + m] = ayr[q];
            g_AYi[(b0 + q)*MDIM + m] = ayi[q];
            g_AYtr[m*BATCH + b0 + q] = ayr[q];
            g_AYti[m*BATCH + b0 + q] = ayi[q];
        }
        // ||Y||^2 per batch: warp wq reduces batch wq
        int wq = tid >> 5, lane = tid & 31;
        float s = 0.f;
        #pragma unroll
        for (int o = 0; o < 4; o++) {
            float yr = sYr[wq][lane + 32*o], yi = sYi[wq][lane + 32*o];
            s += yr*yr + yi*yi;
        }
        #pragma unroll
        for (int o = 16; o > 0; o >>= 1) s += __shfl_down_sync(0xffffffffu, s, o);
        if (lane == 0) g_Yn[b0 + wq] = s;
    }
}

// ---------------- K2: conv1 (2->32, 3x3) + relu, f32x2 h-pairs -------------
__global__ __launch_bounds__(256) void k_conv1(const float* __restrict__ w1,
                                               const float* __restrict__ b1) {
    __shared__ float ws[576];
    __shared__ float bs[32];
    __shared__ float2 px[2*34*11];
    int tid = threadIdx.x;
    int w0 = blockIdx.x * 32;
    int hbase = blockIdx.y * 32;
    for (int idx = tid; idx < 576; idx += 256) ws[idx] = w1[idx];
    if (tid < 32) bs[tid] = b1[tid];
    int wl = tid & 31, og = tid >> 5;
    int oc0 = og * 4;
    for (int hc = 0; hc < 2; hc++) {
        int hb = hbase + hc*16;
        __syncthreads();
        for (int idx = tid; idx < 680; idx += 256) {
            int ic = idx / 340, r = idx % 340, wll = r / 10, t = r % 10;
            int h1 = hb - 1 + t, h2 = h1 + 8;
            int w = w0 - 1 + wll;
            bool wok = (w >= 0 && w < BATCH);
            const float* src = ic ? g_AYti : g_AYtr;
            float v1 = (wok && h1 >= 0 && h1 < MDIM) ? src[h1*BATCH + w] : 0.f;
            float v2 = (wok && h2 < MDIM)            ? src[h2*BATCH + w] : 0.f;
            px[(ic*34 + wll)*11 + t] = make_float2(v1, v2);
        }
        __syncthreads();
        ull acc[4][8];
        #pragma unroll
        for (int o = 0; o < 4; o++) {
            ull bp = pk2(bs[oc0 + o], bs[oc0 + o]);
            #pragma unroll
            for (int p = 0; p < 8; p++) acc[o][p] = bp;
        }
        #pragma unroll
        for (int ic = 0; ic < 2; ic++) {
            #pragma unroll
            for (int kw = 0; kw < 3; kw++) {
                const float2* pp = px + (ic*34 + wl + kw)*11;
                ull xp[10];
                #pragma unroll
                for (int t = 0; t < 10; t++) xp[t] = *(const ull*)(pp + t);
                #pragma unroll
                for (int kh = 0; kh < 3; kh++) {
                    ull wp[4];
                    #pragma unroll
                    for (int o = 0; o < 4; o++) {
                        float wv = ws[(oc0 + o)*18 + ic*9 + kh*3 + kw];
                        wp[o] = pk2(wv, wv);
                    }
                    #pragma unroll
                    for (int p = 0; p < 8; p++) {
                        fma2(acc[0][p], wp[0], xp[p + kh]);
                        fma2(acc[1][p], wp[1], xp[p + kh]);
                        fma2(acc[2][p], wp[2], xp[p + kh]);
                        fma2(acc[3][p], wp[3], xp[p + kh]);
                    }
                }
            }
        }
        #pragma unroll
        for (int o = 0; o < 4; o++) {
            int oc = oc0 + o;
            #pragma unroll
            for (int p = 0; p < 8; p++) {
                float2 v = upk2(acc[o][p]);
                g_F1[(oc*MDIM + hb + p)*BATCH + w0 + wl]     = fmaxf(v.x, 0.f);
                g_F1[(oc*MDIM + hb + 8 + p)*BATCH + w0 + wl] = fmaxf(v.y, 0.f);
            }
        }
    }
}

// ---------------- K3: conv2, h-chunks of 32, pairs (h, h+16) ---------------
#define CP2 19
__global__ __launch_bounds__(256) void k_conv2(const float* __restrict__ w2,
                                               const float* __restrict__ b2) {
    float* wsm = sm2;                          // 9216 floats
    float2* px = (float2*)(sm2 + 9216);        // 32*18*19 float2 = 87552 B
    __shared__ float bs[32];
    int tid = threadIdx.x;
    int w0 = blockIdx.x * 16;
    int by = blockIdx.y;
    int oz = blockIdx.z;
    for (int idx = tid; idx < 9216; idx += 256) wsm[idx] = w2[oz*9216 + idx];
    if (tid < 32) bs[tid] = b2[oz*32 + tid];
    int wl = tid & 15, og = tid >> 4;
    int o0 = og, o1 = og + 16;
    float sum2[2] = {0.f, 0.f};
    for (int hc = 0; hc < 4; hc++) {
        int hb = by*128 + hc*32;
        __syncthreads();
        for (int idx = tid; idx < 10368; idx += 256) {
            int ic = idx / 324, r = idx % 324, t = r / 18, wll = r % 18;
            int h1 = hb - 1 + t, h2 = h1 + 16;
            int w = w0 - 1 + wll;
            bool wok = (w >= 0 && w < BATCH);
            const float* base = g_F1 + (size_t)ic*MDIM*BATCH + w;
            float v1 = (wok && h1 >= 0 && h1 < MDIM) ? base[(size_t)h1*BATCH] : 0.f;
            float v2 = (wok && h2 < MDIM)            ? base[(size_t)h2*BATCH] : 0.f;
            px[(ic*18 + wll)*CP2 + t] = make_float2(v1, v2);
        }
        __syncthreads();
        ull acc[2][16];
        {
            ull b0p = pk2(bs[o0], bs[o0]);
            ull b1p = pk2(bs[o1], bs[o1]);
            #pragma unroll
            for (int p = 0; p < 16; p++) { acc[0][p] = b0p; acc[1][p] = b1p; }
        }
        for (int ic = 0; ic < 32; ic++) {
            const float2* pb = px + (ic*18 + wl)*CP2;
            const float* wb = wsm + ic*9;
            #pragma unroll
            for (int kw = 0; kw < 3; kw++) {
                const float2* pp = pb + kw*CP2;
                ull xp[18];
                #pragma unroll
                for (int t = 0; t < 18; t++) xp[t] = *(const ull*)(pp + t);
                #pragma unroll
                for (int kh = 0; kh < 3; kh++) {
                    float wv0 = wb[o0*288 + kh*3 + kw];
                    float wv1 = wb[o1*288 + kh*3 + kw];
                    ull wp0 = pk2(wv0, wv0);
                    ull wp1 = pk2(wv1, wv1);
                    #pragma unroll
                    for (int p = 0; p < 16; p++) {
                        fma2(acc[0][p], wp0, xp[p + kh]);
                        fma2(acc[1][p], wp1, xp[p + kh]);
                    }
                }
            }
        }
        #pragma unroll
        for (int o = 0; o < 2; o++)
            #pragma unroll
            for (int p = 0; p < 16; p++) {
                float2 v = upk2(acc[o][p]);
                sum2[o] += fmaxf(v.x, 0.f) + fmaxf(v.y, 0.f);
            }
    }
    g_fmp[(by*64 + oz*32 + o0)*BATCH + w0 + wl] = sum2[0] * (1.f / 256.f);
    g_fmp[(by*64 + oz*32 + o1)*BATCH + w0 + wl] = sum2[1] * (1.f / 256.f);
}

// ---------------- K4: conv1d heads + Lam init ------------------------------
__global__ __launch_bounds__(128) void k_heads(
        const float* __restrict__ hcw, const float* __restrict__ hcb,
        const float* __restrict__ hdw, const float* __restrict__ hdb,
        const float* __restrict__ hTw, const float* __restrict__ hTb) {
    float* sf = sm2;              // 64 * 130
    float* sw = sm2 + 64*130;     // 28 * 192
    __shared__ float sb[28];
    __shared__ float slam[128];
    int tid = threadIdx.x;
    int b0 = blockIdx.x * 128;
    for (int idx = tid; idx < 64*130; idx += 128) {
        int ic = idx / 130, off = idx % 130;
        int b = b0 - 1 + off;
        float v = 0.f;
        if (b >= 0 && b < BATCH) v = g_fmp[ic*BATCH + b] + g_fmp[(64 + ic)*BATCH + b];
        sf[idx] = v;
    }
    for (int idx = tid; idx < 28*192; idx += 128) {
        int l = idx / 192, r = idx % 192;
        sw[idx] = (l < 9) ? hcw[l*192 + r] : (l < 18) ? hdw[(l-9)*192 + r] : hTw[(l-18)*192 + r];
    }
    if (tid < 28) sb[tid] = (tid < 9) ? hcb[tid] : (tid < 18) ? hdb[tid-9] : hTb[tid-18];
    __syncthreads();
    float acc[28];
    #pragma unroll
    for (int l = 0; l < 28; l++) acc[l] = sb[l];
    for (int ic = 0; ic < 64; ic++) {
        float x0 = sf[ic*130 + tid];
        float x1 = sf[ic*130 + tid + 1];
        float x2 = sf[ic*130 + tid + 2];
        #pragma unroll
        for (int l = 0; l < 28; l++) {
            const float* w = sw + l*192 + ic*3;
            acc[l] += w[0]*x0 + w[1]*x1 + w[2]*x2;
        }
    }
    int b = b0 + tid;
    float c0 = 0.f, d0 = 0.f;
    #pragma unroll
    for (int l = 0; l < 28; l++) {
        float v = fabsf(acc[l]);
        if (l < 9)       { v = fminf(fmaxf(v, 1e-6f), 100.f); g_c[b*9 + l] = v; if (l == 0) c0 = v; }
        else if (l < 18) { v = fmaxf(v, 1e-6f);               g_d[b*9 + (l-9)] = v; if (l == 9) d0 = v; }
        else             { v = fminf(fmaxf(v, 1e-6f), 100.f); g_T[b*10 + (l-18)] = v; }
    }
    slam[tid] = c0 / d0;
    __syncthreads();
    for (int idx = tid; idx < 128*MDIM; idx += 128)
        g_Lam[b0*MDIM + idx] = slam[idx >> 8];
}

// ---------------- K6: W = AA @ U. 64b x 32i, 128 thr, LDS.128 j-pairs ------
#define GP 18
__global__ __launch_bounds__(128) void k_mm() {
    __shared__ __align__(16) ull sU2[64*GP], sUs[64*GP], sAr[32*GP], sAi[32*GP];
    int tid = threadIdx.x;
    int b0 = blockIdx.x * 64, i0 = blockIdx.y * 32;
    int tx = tid & 7, ty = tid >> 3;
    int lrU = tid >> 1, lcU = (tid & 1) * 8;
    int lrA = tid >> 2, lcA = (tid & 3) * 4;
    float4 fUr0 = *(const float4*)&g_Ur[(b0 + lrU)*MDIM + lcU];
    float4 fUr1 = *(const float4*)&g_Ur[(b0 + lrU)*MDIM + lcU + 4];
    float4 fUi0 = *(const float4*)&g_Ui[(b0 + lrU)*MDIM + lcU];
    float4 fUi1 = *(const float4*)&g_Ui[(b0 + lrU)*MDIM + lcU + 4];
    float4 fAr  = *(const float4*)&g_AAr[(i0 + lrA)*MDIM + lcA];
    float4 fAi  = *(const float4*)&g_AAi[(i0 + lrA)*MDIM + lcA];
    ull acc[4][4];
    #pragma unroll
    for (int u = 0; u < 4; u++)
        #pragma unroll
        for (int v = 0; v < 4; v++) acc[u][v] = 0ull;
    for (int jc = 0; jc < MDIM; jc += 16) {
        __syncthreads();
        {
            float ur[8] = {fUr0.x, fUr0.y, fUr0.z, fUr0.w, fUr1.x, fUr1.y, fUr1.z, fUr1.w};
            float ui[8] = {fUi0.x, fUi0.y, fUi0.z, fUi0.w, fUi1.x, fUi1.y, fUi1.z, fUi1.w};
            float ar[4] = {fAr.x, fAr.y, fAr.z, fAr.w};
            float ai[4] = {fAi.x, fAi.y, fAi.z, fAi.w};
            #pragma unroll
            for (int t = 0; t < 8; t++) {
                sU2[lrU*GP + lcU + t] = pk2(ur[t], ui[t]);
                sUs[lrU*GP + lcU + t] = pk2(-ui[t], ur[t]);
            }
            #pragma unroll
            for (int t = 0; t < 4; t++) {
                sAr[lrA*GP + lcA + t] = pk2(ar[t], ar[t]);
                sAi[lrA*GP + lcA + t] = pk2(ai[t], ai[t]);
            }
        }
        __syncthreads();
        if (jc + 16 < MDIM) {
            int cU = jc + 16 + lcU, cA = jc + 16 + lcA;
            fUr0 = *(const float4*)&g_Ur[(b0 + lrU)*MDIM + cU];
            fUr1 = *(const float4*)&g_Ur[(b0 + lrU)*MDIM + cU + 4];
            fUi0 = *(const float4*)&g_Ui[(b0 + lrU)*MDIM + cU];
            fUi1 = *(const float4*)&g_Ui[(b0 + lrU)*MDIM + cU + 4];
            fAr  = *(const float4*)&g_AAr[(i0 + lrA)*MDIM + cA];
            fAi  = *(const float4*)&g_AAi[(i0 + lrA)*MDIM + cA];
        }
        #pragma unroll
        for (int j = 0; j < 16; j += 2) {
            ulonglong2 u2p[4], usp[4], arp[4], aip[4];
            #pragma unroll
            for (int u = 0; u < 4; u++) {
                u2p[u] = *(const ulonglong2*)&sU2[(ty + 16*u)*GP + j];
                usp[u] = *(const ulonglong2*)&sUs[(ty + 16*u)*GP + j];
            }
            #pragma unroll
            for (int v = 0; v < 4; v++) {
                arp[v] = *(const ulonglong2*)&sAr[(tx + 8*v)*GP + j];
                aip[v] = *(const ulonglong2*)&sAi[(tx + 8*v)*GP + j];
            }
            #pragma unroll
            for (int v = 0; v < 4; v++)
                #pragma unroll
                for (int u = 0; u < 4; u++) {
                    fma2(acc[u][v], arp[v].x, u2p[u].x);
                    fma2(acc[u][v], aip[v].x, usp[u].x);
                }
            #pragma unroll
            for (int v = 0; v < 4; v++)
                #pragma unroll
                for (int u = 0; u < 4; u++) {
                    fma2(acc[u][v], arp[v].y, u2p[u].y);
                    fma2(acc[u][v], aip[v].y, usp[u].y);
                }
        }
    }
    #pragma unroll
    for (int u = 0; u < 4; u++) {
        int b = b0 + ty + 16*u;
        #pragma unroll
        for (int v = 0; v < 4; v++) {
            int i = i0 + tx + 8*v;
            float2 cc = upk2(acc[u][v]);
            g_Wr[b*MDIM + i] = cc.x;
            g_Wi[b*MDIM + i] = cc.y;
        }
    }
}

// ---------------- K7: fused update ----------------------------------------
__global__ __launch_bounds__(256) void k_up(int k,
        const float* __restrict__ a0p, const float* __restrict__ b0p,
        float* __restrict__ out) {
    int b = blockIdx.x, i = threadIdx.x;
    __shared__ float sr1[8];
    __shared__ float sEps;
    int lane = i & 31, w = i >> 5;
    float ur = 0.f, ui = 0.f, wr = 0.f, wi = 0.f;
    if (k > 0) {
        ur = g_Ur[b*MDIM + i]; ui = g_Ui[b*MDIM + i];
        wr = g_Wr[b*MDIM + i];
        wi = g_Wi[b*MDIM + i];
    }
    float ayr = g_AYr[b*MDIM + i], ayi = g_AYi[b*MDIM + i];
    float lam = g_Lam[b*MDIM + i];
    float Dm = g_D[i];
    float eps;
    if (k > 0) {
        float loc = ur*wr + ui*wi - 2.f*(ayr*ur + ayi*ui);
        #pragma unroll
        for (int o = 16; o > 0; o >>= 1) loc += __shfl_down_sync(0xffffffffu, loc, o);
        if (lane == 0) sr1[w] = loc;
        __syncthreads();
        if (i == 0) {
            float s = 0.f;
            #pragma unroll
            for (int q = 0; q < 8; q++) s += sr1[q];
            float eps1 = g_Yn[b] + s;
            float a = a0p[0] + (float)NMEAS;
            sEps = a / (b0p[0] + eps1 + g_eps2[b] + 1e-6f);
        }
        __syncthreads();
        eps = sEps;
    } else {
        eps = a0p[0] / b0p[0];
    }
    float sig = 1.f / (eps*Dm + lam + 1e-6f);
    float Tk = g_T[b*10 + k];
    float inv = eps / (eps*Tk + lam + 1e-6f);
    float unr = inv * (Tk*ur - wr + ayr);
    float uni = inv * (Tk*ui - wi + ayi);
    if (k < LNUM - 1) {
        float v = Dm * sig;
        #pragma unroll
        for (int o = 16; o > 0; o >>= 1) v += __shfl_down_sync(0xffffffffu, v, o);
        __syncthreads();
        if (lane == 0) sr1[w] = v;
        __syncthreads();
        if (i == 0) {
            float s = 0.f;
            #pragma unroll
            for (int q = 0; q < 8; q++) s += sr1[q];
            g_eps2[b] = s;
        }
        g_Ur[b*MDIM + i] = unr;
        g_Ui[b*MDIM + i] = uni;
        float ck = g_c[b*9 + k], dk = g_d[b*9 + k];
        g_Lam[b*MDIM + i] = (ck + 1.f) / (dk + unr*unr + uni*uni + sig + 1e-6f);
    } else {
        float v = sqrtf(unr*unr + uni*uni);
        out[b*MDIM + i] = v;
        float mv = v;
        #pragma unroll
        for (int o = 16; o > 0; o >>= 1) mv = fmaxf(mv, __shfl_down_sync(0xffffffffu, mv, o));
        __syncthreads();
        if (lane == 0) sr1[w] = mv;
        __syncthreads();
        if (i == 0) {
            float s = sr1[0];
            #pragma unroll
            for (int q = 1; q < 8; q++) s = fmaxf(s, sr1[q]);
            atomicMax(&g_max, __float_as_uint(s));
        }
    }
}

// ---------------- K10: scale + diagnostic tails ----------------------------
__global__ void k_final(float* __restrict__ out) {
    int bid = blockIdx.x;
    if (bid < BATCH) {
        int idx = bid * 256 + threadIdx.x;
        float mx = __uint_as_float(g_max);
        out[idx] = out[idx] / (mx + 1e-8f);
    } else {
        int t = threadIdx.x;
        int base = BATCH * MDIM;
        if (t < 9)       out[base + t] = g_c[(BATCH - 1)*9 + t];
        else if (t < 18) out[base + t] = g_d[(BATCH - 1)*9 + (t - 9)];
        else if (t < 28) out[base + t] = g_T[(BATCH - 1)*10 + (t - 18)];
    }
}

// ---------------- launch ---------------------------------------------------
extern "C" void kernel_launch(void* const* d_in, const int* in_sizes, int n_in,
                              void* d_out, int out_size) {
    const float* Yr  = (const float*)d_in[0];
    const float* Yi  = (const float*)d_in[1];
    const float* Ar  = (const float*)d_in[2];
    const float* Ai  = (const float*)d_in[3];
    const float* c1w = (const float*)d_in[4];
    const float* c1b = (const float*)d_in[5];
    const float* c2w = (const float*)d_in[6];
    const float* c2b = (const float*)d_in[7];
    const float* hcw = (const float*)d_in[8];
    const float* hcb = (const float*)d_in[9];
    const float* hdw = (const float*)d_in[10];
    const float* hdb = (const float*)d_in[11];
    const float* hTw = (const float*)d_in[12];
    const float* hTb = (const float*)d_in[13];
    const float* a0  = (const float*)d_in[14];
    const float* b0  = (const float*)d_in[15];
    float* out = (float*)d_out;

    int conv2_smem = 9216*4 + 32*18*CP2*8;              // 36864 + 87552 = 124416
    int heads_smem = (64*130 + 28*192)*4;               // 54784
    cudaFuncSetAttribute(k_conv2, cudaFuncAttributeMaxDynamicSharedMemorySize, conv2_smem);
    cudaFuncSetAttribute(k_heads, cudaFuncAttributeMaxDynamicSharedMemorySize, heads_smem);

    k_front<<<512, 256>>>(Yr, Yi, Ar, Ai);
    k_conv1<<<dim3(64, 8), 256>>>(c1w, c1b);
    k_conv2<<<dim3(128, 2, 2), 256, conv2_smem>>>(c2w, c2b);
    k_heads<<<16, 128, heads_smem>>>(hcw, hcb, hdw, hdb, hTw, hTb);

    for (int k = 0; k < LNUM; k++) {
        if (k > 0) k_mm<<<dim3(32, 8), 128>>>();
        k_up<<<BATCH, 256>>>(k, a0, b0, out);
    }
    k_final<<<2049, 256>>>(out);
}

// round 15
// speedup vs baseline: 1.1146x; 1.1146x over previous
#include <cuda_runtime.h>
#include <math.h>

#define BATCH 2048
#define NMEAS 128
#define MDIM  256
#define LNUM  10

typedef unsigned long long ull;

__device__ __forceinline__ ull pk2(float x, float y) {
    ull r; asm("mov.b64 %0, {%1, %2};" : "=l"(r) : "f"(x), "f"(y)); return r;
}
__device__ __forceinline__ float2 upk2(ull v) {
    float2 t; asm("mov.b64 {%0, %1}, %2;" : "=f"(t.x), "=f"(t.y) : "l"(v)); return t;
}
__device__ __forceinline__ void fma2(ull& d, ull a, ull b) {
    asm("fma.rn.f32x2 %0, %1, %2, %3;" : "=l"(d) : "l"(a), "l"(b), "l"(d));
}

// ---------------- scratch ----------------
__device__ float g_AAr[MDIM*MDIM], g_AAi[MDIM*MDIM];
__device__ float g_D[MDIM];
__device__ float g_AYr[BATCH*MDIM], g_AYi[BATCH*MDIM];
__device__ float g_AYtr[MDIM*BATCH], g_AYti[MDIM*BATCH];
__device__ float g_F1[32*MDIM*BATCH];
__device__ float g_fmp[2*64*BATCH];
__device__ float g_c[BATCH*9], g_d[BATCH*9], g_T[BATCH*10];
__device__ float g_Ur[BATCH*MDIM], g_Ui[BATCH*MDIM];
__device__ float g_Wr[BATCH*MDIM], g_Wi[BATCH*MDIM];
__device__ float g_Lam[BATCH*MDIM];
__device__ float g_eps2[BATCH], g_Yn[BATCH];
__device__ unsigned int g_max;

extern __shared__ float sm2[];

// ---------------- K0: fused prep (AA,D) + AY (independent halves) ----------
__global__ void k_front(const float* __restrict__ Yr, const float* __restrict__ Yi,
                        const float* __restrict__ Ar, const float* __restrict__ Ai) {
    if (blockIdx.x < 256) {
        int i = blockIdx.x, j = threadIdx.x;
        __shared__ float cr[NMEAS], ci[NMEAS];
        if (j < NMEAS) { cr[j] = Ar[j*MDIM + i]; ci[j] = Ai[j*MDIM + i]; }
        __syncthreads();
        float sr = 0.f, si = 0.f;
        for (int n = 0; n < NMEAS; n++) {
            float arj = Ar[n*MDIM + j], aij = Ai[n*MDIM + j];
            sr += cr[n]*arj + ci[n]*aij;
            si += cr[n]*aij - ci[n]*arj;
        }
        g_AAr[i*MDIM + j] = sr;
        g_AAi[i*MDIM + j] = si;
        if (j == i) g_D[i] = sr;
        if (i == 0 && j == 0) g_max = 0u;
    } else {
        int b0 = (blockIdx.x - 256) * 8;
        int tid = threadIdx.x;
        __shared__ float sYr[8][NMEAS], sYi[8][NMEAS];
        for (int idx = tid; idx < 8*NMEAS; idx += 256) {
            int bl = idx >> 7, n = idx & 127;
            sYr[bl][n] = Yr[(b0 + bl)*NMEAS + n];
            sYi[bl][n] = Yi[(b0 + bl)*NMEAS + n];
        }
        __syncthreads();
        int m = tid;
        float ayr[8], ayi[8];
        #pragma unroll
        for (int q = 0; q < 8; q++) { ayr[q] = 0.f; ayi[q] = 0.f; }
        for (int n = 0; n < NMEAS; n++) {
            float ar = Ar[n*MDIM + m], ai = Ai[n*MDIM + m];
            #pragma unroll
            for (int q = 0; q < 8; q++) {
                float yr = sYr[q][n], yi = sYi[q][n];
                ayr[q] += ar*yr + ai*yi;
                ayi[q] += ar*yi - ai*yr;
            }
        }
        #pragma unroll
        for (int q = 0; q < 8; q++) {
            g_AYr[(b0 + q)*MDIM + m] = ayr[q];
            g_AYi[(b0 + q)*MDIM + m] = ayi[q];
            g_AYtr[m*BATCH + b0 + q] = ayr[q];
            g_AYti[m*BATCH + b0 + q] = ayi[q];
        }
    }
}

// ---------------- K2: conv1 (2->32, 3x3) + relu, f32x2 h-pairs -------------
__global__ __launch_bounds__(256) void k_conv1(const float* __restrict__ w1,
                                               const float* __restrict__ b1) {
    __shared__ float ws[576];
    __shared__ float bs[32];
    __shared__ float2 px[2*34*11];
    int tid = threadIdx.x;
    int w0 = blockIdx.x * 32;
    int hbase = blockIdx.y * 32;
    for (int idx = tid; idx < 576; idx += 256) ws[idx] = w1[idx];
    if (tid < 32) bs[tid] = b1[tid];
    int wl = tid & 31, og = tid >> 5;
    int oc0 = og * 4;
    for (int hc = 0; hc < 2; hc++) {
        int hb = hbase + hc*16;
        __syncthreads();
        for (int idx = tid; idx < 680; idx += 256) {
            int ic = idx / 340, r = idx % 340, wll = r / 10, t = r % 10;
            int h1 = hb - 1 + t, h2 = h1 + 8;
            int w = w0 - 1 + wll;
            bool wok = (w >= 0 && w < BATCH);
            const float* src = ic ? g_AYti : g_AYtr;
            float v1 = (wok && h1 >= 0 && h1 < MDIM) ? src[h1*BATCH + w] : 0.f;
            float v2 = (wok && h2 < MDIM)            ? src[h2*BATCH + w] : 0.f;
            px[(ic*34 + wll)*11 + t] = make_float2(v1, v2);
        }
        __syncthreads();
        ull acc[4][8];
        #pragma unroll
        for (int o = 0; o < 4; o++) {
            ull bp = pk2(bs[oc0 + o], bs[oc0 + o]);
            #pragma unroll
            for (int p = 0; p < 8; p++) acc[o][p] = bp;
        }
        #pragma unroll
        for (int ic = 0; ic < 2; ic++) {
            #pragma unroll
            for (int kw = 0; kw < 3; kw++) {
                const float2* pp = px + (ic*34 + wl + kw)*11;
                ull xp[10];
                #pragma unroll
                for (int t = 0; t < 10; t++) xp[t] = *(const ull*)(pp + t);
                #pragma unroll
                for (int kh = 0; kh < 3; kh++) {
                    ull wp[4];
                    #pragma unroll
                    for (int o = 0; o < 4; o++) {
                        float wv = ws[(oc0 + o)*18 + ic*9 + kh*3 + kw];
                        wp[o] = pk2(wv, wv);
                    }
                    #pragma unroll
                    for (int p = 0; p < 8; p++) {
                        fma2(acc[0][p], wp[0], xp[p + kh]);
                        fma2(acc[1][p], wp[1], xp[p + kh]);
                        fma2(acc[2][p], wp[2], xp[p + kh]);
                        fma2(acc[3][p], wp[3], xp[p + kh]);
                    }
                }
            }
        }
        #pragma unroll
        for (int o = 0; o < 4; o++) {
            int oc = oc0 + o;
            #pragma unroll
            for (int p = 0; p < 8; p++) {
                float2 v = upk2(acc[o][p]);
                g_F1[(oc*MDIM + hb + p)*BATCH + w0 + wl]     = fmaxf(v.x, 0.f);
                g_F1[(oc*MDIM + hb + 8 + p)*BATCH + w0 + wl] = fmaxf(v.y, 0.f);
            }
        }
    }
}

// ---------------- K3: conv2 (R7 verbatim) ----------------------------------
#define CPITCH 11
__global__ __launch_bounds__(256) void k_conv2(const float* __restrict__ w2,
                                               const float* __restrict__ b2) {
    float* wsm = sm2;                          // 9216 floats (32 oc)
    float2* px = (float2*)(sm2 + 9216);        // 32*18*11 float2
    __shared__ float bs[32];
    int tid = threadIdx.x;
    int w0 = blockIdx.x * 16;
    int by = blockIdx.y;
    int oz = blockIdx.z;
    for (int idx = tid; idx < 9216; idx += 256) wsm[idx] = w2[oz*9216 + idx];
    if (tid < 32) bs[tid] = b2[oz*32 + tid];
    int wl = tid & 15, og = tid >> 4;
    int o0 = og, o1 = og + 16;
    float sum2[2] = {0.f, 0.f};
    for (int hc = 0; hc < 8; hc++) {
        int hb = by*128 + hc*16;
        __syncthreads();
        for (int idx = tid; idx < 5760; idx += 256) {
            int ic = idx / 180, r = idx % 180, t = r / 18, wll = r % 18;
            int h1 = hb - 1 + t, h2 = h1 + 8;
            int w = w0 - 1 + wll;
            bool wok = (w >= 0 && w < BATCH);
            const float* base = g_F1 + (size_t)ic*MDIM*BATCH + w;
            float v1 = (wok && h1 >= 0 && h1 < MDIM) ? base[(size_t)h1*BATCH] : 0.f;
            float v2 = (wok && h2 < MDIM)            ? base[(size_t)h2*BATCH] : 0.f;
            px[(ic*18 + wll)*CPITCH + t] = make_float2(v1, v2);
        }
        __syncthreads();
        ull acc[2][8];
        {
            ull b0p = pk2(bs[o0], bs[o0]);
            ull b1p = pk2(bs[o1], bs[o1]);
            #pragma unroll
            for (int p = 0; p < 8; p++) { acc[0][p] = b0p; acc[1][p] = b1p; }
        }
        for (int ic = 0; ic < 32; ic++) {
            const float2* pb = px + (ic*18 + wl)*CPITCH;
            const float* wb = wsm + ic*9;
            #pragma unroll
            for (int kw = 0; kw < 3; kw++) {
                const float2* pp = pb + kw*CPITCH;
                ull xp[10];
                #pragma unroll
                for (int t = 0; t < 10; t++) xp[t] = *(const ull*)(pp + t);
                #pragma unroll
                for (int kh = 0; kh < 3; kh++) {
                    float wv0 = wb[o0*288 + kh*3 + kw];
                    float wv1 = wb[o1*288 + kh*3 + kw];
                    ull wp0 = pk2(wv0, wv0);
                    ull wp1 = pk2(wv1, wv1);
                    #pragma unroll
                    for (int p = 0; p < 8; p++) {
                        fma2(acc[0][p], wp0, xp[p + kh]);
                        fma2(acc[1][p], wp1, xp[p + kh]);
                    }
                }
            }
        }
        #pragma unroll
        for (int o = 0; o < 2; o++)
            #pragma unroll
            for (int p = 0; p < 8; p++) {
                float2 v = upk2(acc[o][p]);
                sum2[o] += fmaxf(v.x, 0.f) + fmaxf(v.y, 0.f);
            }
    }
    g_fmp[(by*64 + oz*32 + o0)*BATCH + w0 + wl] = sum2[0] * (1.f / 256.f);
    g_fmp[(by*64 + oz*32 + o1)*BATCH + w0 + wl] = sum2[1] * (1.f / 256.f);
}

// ---------------- K4: conv1d heads --------------------------------
__global__ __launch_bounds__(128) void k_heads(
        const float* __restrict__ hcw, const float* __restrict__ hcb,
        const float* __restrict__ hdw, const float* __restrict__ hdb,
        const float* __restrict__ hTw, const float* __restrict__ hTb) {
    float* sf = sm2;              // 64 * 130
    float* sw = sm2 + 64*130;     // 28 * 192
    __shared__ float sb[28];
    int tid = threadIdx.x;
    int b0 = blockIdx.x * 128;
    for (int idx = tid; idx < 64*130; idx += 128) {
        int ic = idx / 130, off = idx % 130;
        int b = b0 - 1 + off;
        float v = 0.f;
        if (b >= 0 && b < BATCH) v = g_fmp[ic*BATCH + b] + g_fmp[(64 + ic)*BATCH + b];
        sf[idx] = v;
    }
    for (int idx = tid; idx < 28*192; idx += 128) {
        int l = idx / 192, r = idx % 192;
        sw[idx] = (l < 9) ? hcw[l*192 + r] : (l < 18) ? hdw[(l-9)*192 + r] : hTw[(l-18)*192 + r];
    }
    if (tid < 28) sb[tid] = (tid < 9) ? hcb[tid] : (tid < 18) ? hdb[tid-9] : hTb[tid-18];
    __syncthreads();
    float acc[28];
    #pragma unroll
    for (int l = 0; l < 28; l++) acc[l] = sb[l];
    for (int ic = 0; ic < 64; ic++) {
        float x0 = sf[ic*130 + tid];
        float x1 = sf[ic*130 + tid + 1];
        float x2 = sf[ic*130 + tid + 2];
        #pragma unroll
        for (int l = 0; l < 28; l++) {
            const float* w = sw + l*192 + ic*3;
            acc[l] += w[0]*x0 + w[1]*x1 + w[2]*x2;
        }
    }
    int b = b0 + tid;
    #pragma unroll
    for (int l = 0; l < 28; l++) {
        float v = fabsf(acc[l]);
        if (l < 9)       { v = fminf(fmaxf(v, 1e-6f), 100.f); g_c[b*9 + l] = v; }
        else if (l < 18) { v = fmaxf(v, 1e-6f);               g_d[b*9 + (l-9)] = v; }
        else             { v = fminf(fmaxf(v, 1e-6f), 100.f); g_T[b*10 + (l-18)] = v; }
    }
}

// ---------------- K5: init: Lam, ||Y||^2 ----------------------------------
__global__ void k_init(const float* __restrict__ Yr, const float* __restrict__ Yi) {
    int b = blockIdx.x, i = threadIdx.x;
    __shared__ float sred[8];
    float lam = g_c[b*9] / g_d[b*9];
    g_Lam[b*MDIM + i] = lam;
    float v = 0.f;
    if (i < NMEAS) {
        float yr = Yr[b*NMEAS + i], yi = Yi[b*NMEAS + i];
        v = yr*yr + yi*yi;
    }
    int lane = i & 31, w = i >> 5;
    #pragma unroll
    for (int o = 16; o > 0; o >>= 1) v += __shfl_down_sync(0xffffffffu, v, o);
    if (lane == 0) sred[w] = v;
    __syncthreads();
    if (i == 0) {
        float s = 0.f;
        #pragma unroll
        for (int w2 = 0; w2 < 8; w2++) s += sred[w2];
        g_Yn[b] = s;
    }
}

// ---------------- K6: W = AA @ U. 64b x 32i tiles, 128 thr, grid (32,8) ----
#define GP 17
__global__ __launch_bounds__(128) void k_mm() {
    __shared__ ull sU2[64*GP], sUs[64*GP], sA2[32*GP];
    int tid = threadIdx.x;
    int b0 = blockIdx.x * 64, i0 = blockIdx.y * 32;
    int tx = tid & 7, ty = tid >> 3;
    int lrU = tid >> 1, lcU = (tid & 1) * 8;
    int lrA = tid >> 2, lcA = (tid & 3) * 4;
    float4 fUr0 = *(const float4*)&g_Ur[(b0 + lrU)*MDIM + lcU];
    float4 fUr1 = *(const float4*)&g_Ur[(b0 + lrU)*MDIM + lcU + 4];
    float4 fUi0 = *(const float4*)&g_Ui[(b0 + lrU)*MDIM + lcU];
    float4 fUi1 = *(const float4*)&g_Ui[(b0 + lrU)*MDIM + lcU + 4];
    float4 fAr  = *(const float4*)&g_AAr[(i0 + lrA)*MDIM + lcA];
    float4 fAi  = *(const float4*)&g_AAi[(i0 + lrA)*MDIM + lcA];
    ull acc[4][4];
    #pragma unroll
    for (int u = 0; u < 4; u++)
        #pragma unroll
        for (int v = 0; v < 4; v++) acc[u][v] = 0ull;
    for (int jc = 0; jc < MDIM; jc += 16) {
        __syncthreads();
        {
            float ur[8] = {fUr0.x, fUr0.y, fUr0.z, fUr0.w, fUr1.x, fUr1.y, fUr1.z, fUr1.w};
            float ui[8] = {fUi0.x, fUi0.y, fUi0.z, fUi0.w, fUi1.x, fUi1.y, fUi1.z, fUi1.w};
            float ar[4] = {fAr.x, fAr.y, fAr.z, fAr.w};
            float ai[4] = {fAi.x, fAi.y, fAi.z, fAi.w};
            #pragma unroll
            for (int t = 0; t < 8; t++) {
                sU2[lrU*GP + lcU + t] = pk2(ur[t], ui[t]);
                sUs[lrU*GP + lcU + t] = pk2(-ui[t], ur[t]);
            }
            #pragma unroll
            for (int t = 0; t < 4; t++)
                sA2[lrA*GP + lcA + t] = pk2(ar[t], ai[t]);
        }
        __syncthreads();
        if (jc + 16 < MDIM) {
            int cU = jc + 16 + lcU, cA = jc + 16 + lcA;
            fUr0 = *(const float4*)&g_Ur[(b0 + lrU)*MDIM + cU];
            fUr1 = *(const float4*)&g_Ur[(b0 + lrU)*MDIM + cU + 4];
            fUi0 = *(const float4*)&g_Ui[(b0 + lrU)*MDIM + cU];
            fUi1 = *(const float4*)&g_Ui[(b0 + lrU)*MDIM + cU + 4];
            fAr  = *(const float4*)&g_AAr[(i0 + lrA)*MDIM + cA];
            fAi  = *(const float4*)&g_AAi[(i0 + lrA)*MDIM + cA];
        }
        #pragma unroll 4
        for (int j = 0; j < 16; j++) {
            ull u2[4], us[4];
            #pragma unroll
            for (int u = 0; u < 4; u++) {
                u2[u] = sU2[(ty + 16*u)*GP + j];
                us[u] = sUs[(ty + 16*u)*GP + j];
            }
            #pragma unroll
            for (int v = 0; v < 4; v++) {
                float2 a = upk2(sA2[(tx + 8*v)*GP + j]);
                ull arr = pk2(a.x, a.x);
                ull aii = pk2(a.y, a.y);
                #pragma unroll
                for (int u = 0; u < 4; u++) {
                    fma2(acc[u][v], arr, u2[u]);
                    fma2(acc[u][v], aii, us[u]);
                }
            }
        }
    }
    #pragma unroll
    for (int u = 0; u < 4; u++) {
        int b = b0 + ty + 16*u;
        #pragma unroll
        for (int v = 0; v < 4; v++) {
            int i = i0 + tx + 8*v;
            float2 cc = upk2(acc[u][v]);
            g_Wr[b*MDIM + i] = cc.x;
            g_Wi[b*MDIM + i] = cc.y;
        }
    }
}

// ---------------- K7: fused update: eps, Sigma, eps2, U (in place), Lam ----
__global__ __launch_bounds__(256) void k_up(int k,
        const float* __restrict__ a0p, const float* __restrict__ b0p,
        float* __restrict__ out) {
    int b = blockIdx.x, i = threadIdx.x;
    __shared__ float sr1[8];
    __shared__ float sEps;
    int lane = i & 31, w = i >> 5;
    float ur = 0.f, ui = 0.f, wr = 0.f, wi = 0.f;
    if (k > 0) {
        ur = g_Ur[b*MDIM + i]; ui = g_Ui[b*MDIM + i];
        wr = g_Wr[b*MDIM + i];
        wi = g_Wi[b*MDIM + i];
    }
    float ayr = g_AYr[b*MDIM + i], ayi = g_AYi[b*MDIM + i];
    float lam = g_Lam[b*MDIM + i];
    float Dm = g_D[i];
    float eps;
    if (k > 0) {
        float loc = ur*wr + ui*wi - 2.f*(ayr*ur + ayi*ui);
        #pragma unroll
        for (int o = 16; o > 0; o >>= 1) loc += __shfl_down_sync(0xffffffffu, loc, o);
        if (lane == 0) sr1[w] = loc;
        __syncthreads();
        if (i == 0) {
            float s = 0.f;
            #pragma unroll
            for (int q = 0; q < 8; q++) s += sr1[q];
            float eps1 = g_Yn[b] + s;
            float a = a0p[0] + (float)NMEAS;
            sEps = a / (b0p[0] + eps1 + g_eps2[b] + 1e-6f);
        }
        __syncthreads();
        eps = sEps;
    } else {
        eps = a0p[0] / b0p[0];
    }
    float sig = 1.f / (eps*Dm + lam + 1e-6f);
    float Tk = g_T[b*10 + k];
    float inv = eps / (eps*Tk + lam + 1e-6f);
    float unr = inv * (Tk*ur - wr + ayr);
    float uni = inv * (Tk*ui - wi + ayi);
    if (k < LNUM - 1) {
        float v = Dm * sig;
        #pragma unroll
        for (int o = 16; o > 0; o >>= 1) v += __shfl_down_sync(0xffffffffu, v, o);
        __syncthreads();
        if (lane == 0) sr1[w] = v;
        __syncthreads();
        if (i == 0) {
            float s = 0.f;
            #pragma unroll
            for (int q = 0; q < 8; q++) s += sr1[q];
            g_eps2[b] = s;
        }
        g_Ur[b*MDIM + i] = unr;
        g_Ui[b*MDIM + i] = uni;
        float ck = g_c[b*9 + k], dk = g_d[b*9 + k];
        g_Lam[b*MDIM + i] = (ck + 1.f) / (dk + unr*unr + uni*uni + sig + 1e-6f);
    } else {
        float v = sqrtf(unr*unr + uni*uni);
        out[b*MDIM + i] = v;
        float mv = v;
        #pragma unroll
        for (int o = 16; o > 0; o >>= 1) mv = fmaxf(mv, __shfl_down_sync(0xffffffffu, mv, o));
        __syncthreads();
        if (lane == 0) sr1[w] = mv;
        __syncthreads();
        if (i == 0) {
            float s = sr1[0];
            #pragma unroll
            for (int q = 1; q < 8; q++) s = fmaxf(s, sr1[q]);
            atomicMax(&g_max, __float_as_uint(s));
        }
    }
}

// ---------------- K10: scale + diagnostic tails ----------------------------
__global__ void k_final(float* __restrict__ out) {
    int bid = blockIdx.x;
    if (bid < BATCH) {
        int idx = bid * 256 + threadIdx.x;
        float mx = __uint_as_float(g_max);
        out[idx] = out[idx] / (mx + 1e-8f);
    } else {
        int t = threadIdx.x;
        int base = BATCH * MDIM;
        if (t < 9)       out[base + t] = g_c[(BATCH - 1)*9 + t];
        else if (t < 18) out[base + t] = g_d[(BATCH - 1)*9 + (t - 9)];
        else if (t < 28) out[base + t] = g_T[(BATCH - 1)*10 + (t - 18)];
    }
}

// ---------------- launch ---------------------------------------------------
extern "C" void kernel_launch(void* const* d_in, const int* in_sizes, int n_in,
                              void* d_out, int out_size) {
    const float* Yr  = (const float*)d_in[0];
    const float* Yi  = (const float*)d_in[1];
    const float* Ar  = (const float*)d_in[2];
    const float* Ai  = (const float*)d_in[3];
    const float* c1w = (const float*)d_in[4];
    const float* c1b = (const float*)d_in[5];
    const float* c2w = (const float*)d_in[6];
    const float* c2b = (const float*)d_in[7];
    const float* hcw = (const float*)d_in[8];
    const float* hcb = (const float*)d_in[9];
    const float* hdw = (const float*)d_in[10];
    const float* hdb = (const float*)d_in[11];
    const float* hTw = (const float*)d_in[12];
    const float* hTb = (const float*)d_in[13];
    const float* a0  = (const float*)d_in[14];
    const float* b0  = (const float*)d_in[15];
    float* out = (float*)d_out;

    int conv2_smem = 9216*4 + 32*18*CPITCH*8;           // 87552
    int heads_smem = (64*130 + 28*192)*4;               // 54784
    cudaFuncSetAttribute(k_conv2, cudaFuncAttributeMaxDynamicSharedMemorySize, conv2_smem);
    cudaFuncSetAttribute(k_heads, cudaFuncAttributeMaxDynamicSharedMemorySize, heads_smem);

    k_front<<<512, 256>>>(Yr, Yi, Ar, Ai);
    k_conv1<<<dim3(64, 8), 256>>>(c1w, c1b);
    k_conv2<<<dim3(128, 2, 2), 256, conv2_smem>>>(c2w, c2b);
    k_heads<<<16, 128, heads_smem>>>(hcw, hcb, hdw, hdb, hTw, hTb);
    k_init<<<BATCH, 256>>>(Yr, Yi);

    for (int k = 0; k < LNUM; k++) {
        if (k > 0) k_mm<<<dim3(32, 8), 128>>>();
        k_up<<<BATCH, 256>>>(k, a0, b0, out);
    }
    k_final<<<2049, 256>>>(out);
}

// round 16
// speedup vs baseline: 1.1862x; 1.0642x over previous
#include <cuda_runtime.h>
#include <math.h>

#define BATCH 2048
#define NMEAS 128
#define MDIM  256
#define LNUM  10

typedef unsigned long long ull;

__device__ __forceinline__ ull pk2(float x, float y) {
    ull r; asm("mov.b64 %0, {%1, %2};" : "=l"(r) : "f"(x), "f"(y)); return r;
}
__device__ __forceinline__ float2 upk2(ull v) {
    float2 t; asm("mov.b64 {%0, %1}, %2;" : "=f"(t.x), "=f"(t.y) : "l"(v)); return t;
}
__device__ __forceinline__ void fma2(ull& d, ull a, ull b) {
    asm("fma.rn.f32x2 %0, %1, %2, %3;" : "=l"(d) : "l"(a), "l"(b), "l"(d));
}

// ---------------- scratch ----------------
__device__ float g_AAr[MDIM*MDIM], g_AAi[MDIM*MDIM];
__device__ float g_D[MDIM];
__device__ float g_AYr[BATCH*MDIM], g_AYi[BATCH*MDIM];
__device__ float g_AYtr[MDIM*BATCH], g_AYti[MDIM*BATCH];
__device__ float g_F1[32*MDIM*BATCH];
__device__ float g_fmp[2*64*BATCH];
__device__ float g_c[BATCH*9], g_d[BATCH*9], g_T[BATCH*10];
__device__ float g_Ur[BATCH*MDIM], g_Ui[BATCH*MDIM];
__device__ float g_Wr[BATCH*MDIM], g_Wi[BATCH*MDIM];
__device__ float g_Lam[BATCH*MDIM];
__device__ float g_eps2[BATCH], g_Yn[BATCH];
__device__ unsigned int g_max;

extern __shared__ float sm2[];

// ---------------- K0: fused prep (AA,D) + AY (independent halves) ----------
__global__ void k_front(const float* __restrict__ Yr, const float* __restrict__ Yi,
                        const float* __restrict__ Ar, const float* __restrict__ Ai) {
    if (blockIdx.x < 256) {
        int i = blockIdx.x, j = threadIdx.x;
        __shared__ float cr[NMEAS], ci[NMEAS];
        if (j < NMEAS) { cr[j] = Ar[j*MDIM + i]; ci[j] = Ai[j*MDIM + i]; }
        __syncthreads();
        float sr = 0.f, si = 0.f;
        for (int n = 0; n < NMEAS; n++) {
            float arj = Ar[n*MDIM + j], aij = Ai[n*MDIM + j];
            sr += cr[n]*arj + ci[n]*aij;
            si += cr[n]*aij - ci[n]*arj;
        }
        g_AAr[i*MDIM + j] = sr;
        g_AAi[i*MDIM + j] = si;
        if (j == i) g_D[i] = sr;
        if (i == 0 && j == 0) g_max = 0u;
    } else {
        int b0 = (blockIdx.x - 256) * 8;
        int tid = threadIdx.x;
        __shared__ float sYr[8][NMEAS], sYi[8][NMEAS];
        for (int idx = tid; idx < 8*NMEAS; idx += 256) {
            int bl = idx >> 7, n = idx & 127;
            sYr[bl][n] = Yr[(b0 + bl)*NMEAS + n];
            sYi[bl][n] = Yi[(b0 + bl)*NMEAS + n];
        }
        __syncthreads();
        int m = tid;
        float ayr[8], ayi[8];
        #pragma unroll
        for (int q = 0; q < 8; q++) { ayr[q] = 0.f; ayi[q] = 0.f; }
        for (int n = 0; n < NMEAS; n++) {
            float ar = Ar[n*MDIM + m], ai = Ai[n*MDIM + m];
            #pragma unroll
            for (int q = 0; q < 8; q++) {
                float yr = sYr[q][n], yi = sYi[q][n];
                ayr[q] += ar*yr + ai*yi;
                ayi[q] += ar*yi - ai*yr;
            }
        }
        #pragma unroll
        for (int q = 0; q < 8; q++) {
            g_AYr[(b0 + q)*MDIM + m] = ayr[q];
            g_AYi[(b0 + q)*MDIM + m] = ayi[q];
            g_AYtr[m*BATCH + b0 + q] = ayr[q];
            g_AYti[m*BATCH + b0 + q] = ayi[q];
        }
    }
}

// ---------------- K2: conv1 (2->32, 3x3) + relu, f32x2 h-pairs -------------
__global__ __launch_bounds__(256) void k_conv1(const float* __restrict__ w1,
                                               const float* __restrict__ b1) {
    __shared__ float ws[576];
    __shared__ float bs[32];
    __shared__ float2 px[2*34*11];
    int tid = threadIdx.x;
    int w0 = blockIdx.x * 32;
    int hbase = blockIdx.y * 32;
    for (int idx = tid; idx < 576; idx += 256) ws[idx] = w1[idx];
    if (tid < 32) bs[tid] = b1[tid];
    int wl = tid & 31, og = tid >> 5;
    int oc0 = og * 4;
    for (int hc = 0; hc < 2; hc++) {
        int hb = hbase + hc*16;
        __syncthreads();
        for (int idx = tid; idx < 680; idx += 256) {
            int ic = idx / 340, r = idx % 340, wll = r / 10, t = r % 10;
            int h1 = hb - 1 + t, h2 = h1 + 8;
            int w = w0 - 1 + wll;
            bool wok = (w >= 0 && w < BATCH);
            const float* src = ic ? g_AYti : g_AYtr;
            float v1 = (wok && h1 >= 0 && h1 < MDIM) ? src[h1*BATCH + w] : 0.f;
            float v2 = (wok && h2 < MDIM)            ? src[h2*BATCH + w] : 0.f;
            px[(ic*34 + wll)*11 + t] = make_float2(v1, v2);
        }
        __syncthreads();
        ull acc[4][8];
        #pragma unroll
        for (int o = 0; o < 4; o++) {
            ull bp = pk2(bs[oc0 + o], bs[oc0 + o]);
            #pragma unroll
            for (int p = 0; p < 8; p++) acc[o][p] = bp;
        }
        #pragma unroll
        for (int ic = 0; ic < 2; ic++) {
            #pragma unroll
            for (int kw = 0; kw < 3; kw++) {
                const float2* pp = px + (ic*34 + wl + kw)*11;
                ull xp[10];
                #pragma unroll
                for (int t = 0; t < 10; t++) xp[t] = *(const ull*)(pp + t);
                #pragma unroll
                for (int kh = 0; kh < 3; kh++) {
                    ull wp[4];
                    #pragma unroll
                    for (int o = 0; o < 4; o++) {
                        float wv = ws[(oc0 + o)*18 + ic*9 + kh*3 + kw];
                        wp[o] = pk2(wv, wv);
                    }
                    #pragma unroll
                    for (int p = 0; p < 8; p++) {
                        fma2(acc[0][p], wp[0], xp[p + kh]);
                        fma2(acc[1][p], wp[1], xp[p + kh]);
                        fma2(acc[2][p], wp[2], xp[p + kh]);
                        fma2(acc[3][p], wp[3], xp[p + kh]);
                    }
                }
            }
        }
        #pragma unroll
        for (int o = 0; o < 4; o++) {
            int oc = oc0 + o;
            #pragma unroll
            for (int p = 0; p < 8; p++) {
                float2 v = upk2(acc[o][p]);
                g_F1[(oc*MDIM + hb + p)*BATCH + w0 + wl]     = fmaxf(v.x, 0.f);
                g_F1[(oc*MDIM + hb + 8 + p)*BATCH + w0 + wl] = fmaxf(v.y, 0.f);
            }
        }
    }
}

// ---------------- K3: conv2 (R7 verbatim) ----------------------------------
#define CPITCH 11
__global__ __launch_bounds__(256) void k_conv2(const float* __restrict__ w2,
                                               const float* __restrict__ b2) {
    float* wsm = sm2;                          // 9216 floats (32 oc)
    float2* px = (float2*)(sm2 + 9216);        // 32*18*11 float2
    __shared__ float bs[32];
    int tid = threadIdx.x;
    int w0 = blockIdx.x * 16;
    int by = blockIdx.y;
    int oz = blockIdx.z;
    for (int idx = tid; idx < 9216; idx += 256) wsm[idx] = w2[oz*9216 + idx];
    if (tid < 32) bs[tid] = b2[oz*32 + tid];
    int wl = tid & 15, og = tid >> 4;
    int o0 = og, o1 = og + 16;
    float sum2[2] = {0.f, 0.f};
    for (int hc = 0; hc < 8; hc++) {
        int hb = by*128 + hc*16;
        __syncthreads();
        for (int idx = tid; idx < 5760; idx += 256) {
            int ic = idx / 180, r = idx % 180, t = r / 18, wll = r % 18;
            int h1 = hb - 1 + t, h2 = h1 + 8;
            int w = w0 - 1 + wll;
            bool wok = (w >= 0 && w < BATCH);
            const float* base = g_F1 + (size_t)ic*MDIM*BATCH + w;
            float v1 = (wok && h1 >= 0 && h1 < MDIM) ? base[(size_t)h1*BATCH] : 0.f;
            float v2 = (wok && h2 < MDIM)            ? base[(size_t)h2*BATCH] : 0.f;
            px[(ic*18 + wll)*CPITCH + t] = make_float2(v1, v2);
        }
        __syncthreads();
        ull acc[2][8];
        {
            ull b0p = pk2(bs[o0], bs[o0]);
            ull b1p = pk2(bs[o1], bs[o1]);
            #pragma unroll
            for (int p = 0; p < 8; p++) { acc[0][p] = b0p; acc[1][p] = b1p; }
        }
        for (int ic = 0; ic < 32; ic++) {
            const float2* pb = px + (ic*18 + wl)*CPITCH;
            const float* wb = wsm + ic*9;
            #pragma unroll
            for (int kw = 0; kw < 3; kw++) {
                const float2* pp = pb + kw*CPITCH;
                ull xp[10];
                #pragma unroll
                for (int t = 0; t < 10; t++) xp[t] = *(const ull*)(pp + t);
                #pragma unroll
                for (int kh = 0; kh < 3; kh++) {
                    float wv0 = wb[o0*288 + kh*3 + kw];
                    float wv1 = wb[o1*288 + kh*3 + kw];
                    ull wp0 = pk2(wv0, wv0);
                    ull wp1 = pk2(wv1, wv1);
                    #pragma unroll
                    for (int p = 0; p < 8; p++) {
                        fma2(acc[0][p], wp0, xp[p + kh]);
                        fma2(acc[1][p], wp1, xp[p + kh]);
                    }
                }
            }
        }
        #pragma unroll
        for (int o = 0; o < 2; o++)
            #pragma unroll
            for (int p = 0; p < 8; p++) {
                float2 v = upk2(acc[o][p]);
                sum2[o] += fmaxf(v.x, 0.f) + fmaxf(v.y, 0.f);
            }
    }
    g_fmp[(by*64 + oz*32 + o0)*BATCH + w0 + wl] = sum2[0] * (1.f / 256.f);
    g_fmp[(by*64 + oz*32 + o1)*BATCH + w0 + wl] = sum2[1] * (1.f / 256.f);
}

// ---------------- K4: conv1d heads, split across layers (grid.y = 7) -------
__global__ __launch_bounds__(128) void k_heads(
        const float* __restrict__ hcw, const float* __restrict__ hcb,
        const float* __restrict__ hdw, const float* __restrict__ hdb,
        const float* __restrict__ hTw, const float* __restrict__ hTb) {
    float* sf = sm2;              // 64 * 130
    float* sw = sm2 + 64*130;     // 4 * 192
    __shared__ float sb[4];
    int tid = threadIdx.x;
    int b0 = blockIdx.x * 128;
    int l0 = blockIdx.y * 4;      // this block handles layers l0..l0+3
    for (int idx = tid; idx < 64*130; idx += 128) {
        int ic = idx / 130, off = idx % 130;
        int b = b0 - 1 + off;
        float v = 0.f;
        if (b >= 0 && b < BATCH) v = g_fmp[ic*BATCH + b] + g_fmp[(64 + ic)*BATCH + b];
        sf[idx] = v;
    }
    for (int idx = tid; idx < 4*192; idx += 128) {
        int l = l0 + idx / 192, r = idx % 192;
        sw[idx] = (l < 9) ? hcw[l*192 + r] : (l < 18) ? hdw[(l-9)*192 + r] : hTw[(l-18)*192 + r];
    }
    if (tid < 4) {
        int l = l0 + tid;
        sb[tid] = (l < 9) ? hcb[l] : (l < 18) ? hdb[l-9] : hTb[l-18];
    }
    __syncthreads();
    float acc[4];
    #pragma unroll
    for (int q = 0; q < 4; q++) acc[q] = sb[q];
    for (int ic = 0; ic < 64; ic++) {
        float x0 = sf[ic*130 + tid];
        float x1 = sf[ic*130 + tid + 1];
        float x2 = sf[ic*130 + tid + 2];
        #pragma unroll
        for (int q = 0; q < 4; q++) {
            const float* w = sw + q*192 + ic*3;
            acc[q] += w[0]*x0 + w[1]*x1 + w[2]*x2;
        }
    }
    int b = b0 + tid;
    #pragma unroll
    for (int q = 0; q < 4; q++) {
        int l = l0 + q;
        float v = fabsf(acc[q]);
        if (l < 9)       { v = fminf(fmaxf(v, 1e-6f), 100.f); g_c[b*9 + l] = v; }
        else if (l < 18) { v = fmaxf(v, 1e-6f);               g_d[b*9 + (l-9)] = v; }
        else             { v = fminf(fmaxf(v, 1e-6f), 100.f); g_T[b*10 + (l-18)] = v; }
    }
}

// ---------------- K5: init: Lam, ||Y||^2 ----------------------------------
__global__ void k_init(const float* __restrict__ Yr, const float* __restrict__ Yi) {
    int b = blockIdx.x, i = threadIdx.x;
    __shared__ float sred[8];
    float lam = g_c[b*9] / g_d[b*9];
    g_Lam[b*MDIM + i] = lam;
    float v = 0.f;
    if (i < NMEAS) {
        float yr = Yr[b*NMEAS + i], yi = Yi[b*NMEAS + i];
        v = yr*yr + yi*yi;
    }
    int lane = i & 31, w = i >> 5;
    #pragma unroll
    for (int o = 16; o > 0; o >>= 1) v += __shfl_down_sync(0xffffffffu, v, o);
    if (lane == 0) sred[w] = v;
    __syncthreads();
    if (i == 0) {
        float s = 0.f;
        #pragma unroll
        for (int w2 = 0; w2 < 8; w2++) s += sred[w2];
        g_Yn[b] = s;
    }
}

// ---------------- K6: W = AA @ U. 64b x 32i tiles, 128 thr, grid (32,8) ----
#define GP 17
__global__ __launch_bounds__(128) void k_mm() {
    __shared__ ull sU2[64*GP], sUs[64*GP], sA2[32*GP];
    int tid = threadIdx.x;
    int b0 = blockIdx.x * 64, i0 = blockIdx.y * 32;
    int tx = tid & 7, ty = tid >> 3;
    int lrU = tid >> 1, lcU = (tid & 1) * 8;
    int lrA = tid >> 2, lcA = (tid & 3) * 4;
    float4 fUr0 = *(const float4*)&g_Ur[(b0 + lrU)*MDIM + lcU];
    float4 fUr1 = *(const float4*)&g_Ur[(b0 + lrU)*MDIM + lcU + 4];
    float4 fUi0 = *(const float4*)&g_Ui[(b0 + lrU)*MDIM + lcU];
    float4 fUi1 = *(const float4*)&g_Ui[(b0 + lrU)*MDIM + lcU + 4];
    float4 fAr  = *(const float4*)&g_AAr[(i0 + lrA)*MDIM + lcA];
    float4 fAi  = *(const float4*)&g_AAi[(i0 + lrA)*MDIM + lcA];
    ull acc[4][4];
    #pragma unroll
    for (int u = 0; u < 4; u++)
        #pragma unroll
        for (int v = 0; v < 4; v++) acc[u][v] = 0ull;
    for (int jc = 0; jc < MDIM; jc += 16) {
        __syncthreads();
        {
            float ur[8] = {fUr0.x, fUr0.y, fUr0.z, fUr0.w, fUr1.x, fUr1.y, fUr1.z, fUr1.w};
            float ui[8] = {fUi0.x, fUi0.y, fUi0.z, fUi0.w, fUi1.x, fUi1.y, fUi1.z, fUi1.w};
            float ar[4] = {fAr.x, fAr.y, fAr.z, fAr.w};
            float ai[4] = {fAi.x, fAi.y, fAi.z, fAi.w};
            #pragma unroll
            for (int t = 0; t < 8; t++) {
                sU2[lrU*GP + lcU + t] = pk2(ur[t], ui[t]);
                sUs[lrU*GP + lcU + t] = pk2(-ui[t], ur[t]);
            }
            #pragma unroll
            for (int t = 0; t < 4; t++)
                sA2[lrA*GP + lcA + t] = pk2(ar[t], ai[t]);
        }
        __syncthreads();
        if (jc + 16 < MDIM) {
            int cU = jc + 16 + lcU, cA = jc + 16 + lcA;
            fUr0 = *(const float4*)&g_Ur[(b0 + lrU)*MDIM + cU];
            fUr1 = *(const float4*)&g_Ur[(b0 + lrU)*MDIM + cU + 4];
            fUi0 = *(const float4*)&g_Ui[(b0 + lrU)*MDIM + cU];
            fUi1 = *(const float4*)&g_Ui[(b0 + lrU)*MDIM + cU + 4];
            fAr  = *(const float4*)&g_AAr[(i0 + lrA)*MDIM + cA];
            fAi  = *(const float4*)&g_AAi[(i0 + lrA)*MDIM + cA];
        }
        #pragma unroll 4
        for (int j = 0; j < 16; j++) {
            ull u2[4], us[4];
            #pragma unroll
            for (int u = 0; u < 4; u++) {
                u2[u] = sU2[(ty + 16*u)*GP + j];
                us[u] = sUs[(ty + 16*u)*GP + j];
            }
            #pragma unroll
            for (int v = 0; v < 4; v++) {
                float2 a = upk2(sA2[(tx + 8*v)*GP + j]);
                ull arr = pk2(a.x, a.x);
                ull aii = pk2(a.y, a.y);
                #pragma unroll
                for (int u = 0; u < 4; u++) {
                    fma2(acc[u][v], arr, u2[u]);
                    fma2(acc[u][v], aii, us[u]);
                }
            }
        }
    }
    #pragma unroll
    for (int u = 0; u < 4; u++) {
        int b = b0 + ty + 16*u;
        #pragma unroll
        for (int v = 0; v < 4; v++) {
            int i = i0 + tx + 8*v;
            float2 cc = upk2(acc[u][v]);
            g_Wr[b*MDIM + i] = cc.x;
            g_Wi[b*MDIM + i] = cc.y;
        }
    }
}

// ---------------- K7: fused update: eps, Sigma, eps2, U (in place), Lam ----
__global__ __launch_bounds__(256) void k_up(int k,
        const float* __restrict__ a0p, const float* __restrict__ b0p,
        float* __restrict__ out) {
    int b = blockIdx.x, i = threadIdx.x;
    __shared__ float sr1[8];
    __shared__ float sEps;
    int lane = i & 31, w = i >> 5;
    float ur = 0.f, ui = 0.f, wr = 0.f, wi = 0.f;
    if (k > 0) {
        ur = g_Ur[b*MDIM + i]; ui = g_Ui[b*MDIM + i];
        wr = g_Wr[b*MDIM + i];
        wi = g_Wi[b*MDIM + i];
    }
    float ayr = g_AYr[b*MDIM + i], ayi = g_AYi[b*MDIM + i];
    float lam = g_Lam[b*MDIM + i];
    float Dm = g_D[i];
    float eps;
    if (k > 0) {
        float loc = ur*wr + ui*wi - 2.f*(ayr*ur + ayi*ui);
        #pragma unroll
        for (int o = 16; o > 0; o >>= 1) loc += __shfl_down_sync(0xffffffffu, loc, o);
        if (lane == 0) sr1[w] = loc;
        __syncthreads();
        if (i == 0) {
            float s = 0.f;
            #pragma unroll
            for (int q = 0; q < 8; q++) s += sr1[q];
            float eps1 = g_Yn[b] + s;
            float a = a0p[0] + (float)NMEAS;
            sEps = a / (b0p[0] + eps1 + g_eps2[b] + 1e-6f);
        }
        __syncthreads();
        eps = sEps;
    } else {
        eps = a0p[0] / b0p[0];
    }
    float sig = 1.f / (eps*Dm + lam + 1e-6f);
    float Tk = g_T[b*10 + k];
    float inv = eps / (eps*Tk + lam + 1e-6f);
    float unr = inv * (Tk*ur - wr + ayr);
    float uni = inv * (Tk*ui - wi + ayi);
    if (k < LNUM - 1) {
        float v = Dm * sig;
        #pragma unroll
        for (int o = 16; o > 0; o >>= 1) v += __shfl_down_sync(0xffffffffu, v, o);
        __syncthreads();
        if (lane == 0) sr1[w] = v;
        __syncthreads();
        if (i == 0) {
            float s = 0.f;
            #pragma unroll
            for (int q = 0; q < 8; q++) s += sr1[q];
            g_eps2[b] = s;
        }
        g_Ur[b*MDIM + i] = unr;
        g_Ui[b*MDIM + i] = uni;
        float ck = g_c[b*9 + k], dk = g_d[b*9 + k];
        g_Lam[b*MDIM + i] = (ck + 1.f) / (dk + unr*unr + uni*uni + sig + 1e-6f);
    } else {
        float v = sqrtf(unr*unr + uni*uni);
        out[b*MDIM + i] = v;
        float mv = v;
        #pragma unroll
        for (int o = 16; o > 0; o >>= 1) mv = fmaxf(mv, __shfl_down_sync(0xffffffffu, mv, o));
        __syncthreads();
        if (lane == 0) sr1[w] = mv;
        __syncthreads();
        if (i == 0) {
            float s = sr1[0];
            #pragma unroll
            for (int q = 1; q < 8; q++) s = fmaxf(s, sr1[q]);
            atomicMax(&g_max, __float_as_uint(s));
        }
    }
}

// ---------------- K10: scale + diagnostic tails ----------------------------
__global__ void k_final(float* __restrict__ out) {
    int bid = blockIdx.x;
    if (bid < BATCH) {
        int idx = bid * 256 + threadIdx.x;
        float mx = __uint_as_float(g_max);
        out[idx] = out[idx] / (mx + 1e-8f);
    } else {
        int t = threadIdx.x;
        int base = BATCH * MDIM;
        if (t < 9)       out[base + t] = g_c[(BATCH - 1)*9 + t];
        else if (t < 18) out[base + t] = g_d[(BATCH - 1)*9 + (t - 9)];
        else if (t < 28) out[base + t] = g_T[(BATCH - 1)*10 + (t - 18)];
    }
}

// ---------------- launch ---------------------------------------------------
extern "C" void kernel_launch(void* const* d_in, const int* in_sizes, int n_in,
                              void* d_out, int out_size) {
    const float* Yr  = (const float*)d_in[0];
    const float* Yi  = (const float*)d_in[1];
    const float* Ar  = (const float*)d_in[2];
    const float* Ai  = (const float*)d_in[3];
    const float* c1w = (const float*)d_in[4];
    const float* c1b = (const float*)d_in[5];
    const float* c2w = (const float*)d_in[6];
    const float* c2b = (const float*)d_in[7];
    const float* hcw = (const float*)d_in[8];
    const float* hcb = (const float*)d_in[9];
    const float* hdw = (const float*)d_in[10];
    const float* hdb = (const float*)d_in[11];
    const float* hTw = (const float*)d_in[12];
    const float* hTb = (const float*)d_in[13];
    const float* a0  = (const float*)d_in[14];
    const float* b0  = (const float*)d_in[15];
    float* out = (float*)d_out;

    int conv2_smem = 9216*4 + 32*18*CPITCH*8;           // 87552
    int heads_smem = (64*130 + 4*192)*4;                // 36352
    cudaFuncSetAttribute(k_conv2, cudaFuncAttributeMaxDynamicSharedMemorySize, conv2_smem);
    cudaFuncSetAttribute(k_heads, cudaFuncAttributeMaxDynamicSharedMemorySize, heads_smem);

    k_front<<<512, 256>>>(Yr, Yi, Ar, Ai);
    k_conv1<<<dim3(64, 8), 256>>>(c1w, c1b);
    k_conv2<<<dim3(128, 2, 2), 256, conv2_smem>>>(c2w, c2b);
    k_heads<<<dim3(16, 7), 128, heads_smem>>>(hcw, hcb, hdw, hdb, hTw, hTb);
    k_init<<<BATCH, 256>>>(Yr, Yi);

    for (int k = 0; k < LNUM; k++) {
        if (k > 0) k_mm<<<dim3(32, 8), 128>>>();
        k_up<<<BATCH, 256>>>(k, a0, b0, out);
    }
    k_final<<<2049, 256>>>(out);
}

// round 17
// speedup vs baseline: 1.1975x; 1.0095x over previous
#include <cuda_runtime.h>
#include <math.h>

#define BATCH 2048
#define NMEAS 128
#define MDIM  256
#define LNUM  10

typedef unsigned long long ull;

__device__ __forceinline__ ull pk2(float x, float y) {
    ull r; asm("mov.b64 %0, {%1, %2};" : "=l"(r) : "f"(x), "f"(y)); return r;
}
__device__ __forceinline__ float2 upk2(ull v) {
    float2 t; asm("mov.b64 {%0, %1}, %2;" : "=f"(t.x), "=f"(t.y) : "l"(v)); return t;
}
__device__ __forceinline__ void fma2(ull& d, ull a, ull b) {
    asm("fma.rn.f32x2 %0, %1, %2, %3;" : "=l"(d) : "l"(a), "l"(b), "l"(d));
}

// ---------------- scratch ----------------
__device__ float g_AAr[MDIM*MDIM], g_AAi[MDIM*MDIM];
__device__ float g_D[MDIM];
__device__ float g_AYr[BATCH*MDIM], g_AYi[BATCH*MDIM];
__device__ float g_F1[32*MDIM*BATCH];
__device__ float g_fmp[2*64*BATCH];
__device__ float g_c[BATCH*9], g_d[BATCH*9], g_T[BATCH*10];
__device__ float g_Ur[BATCH*MDIM], g_Ui[BATCH*MDIM];
__device__ float g_Wr[BATCH*MDIM], g_Wi[BATCH*MDIM];
__device__ float g_Lam[BATCH*MDIM];
__device__ float g_eps2[BATCH], g_Yn[BATCH];
__device__ unsigned int g_max;

extern __shared__ float sm2[];

// ---------------- K0: fused prep (AA,D) + AY + ||Y||^2 ---------------------
__global__ void k_front(const float* __restrict__ Yr, const float* __restrict__ Yi,
                        const float* __restrict__ Ar, const float* __restrict__ Ai) {
    if (blockIdx.x < 256) {
        int i = blockIdx.x, j = threadIdx.x;
        __shared__ float cr[NMEAS], ci[NMEAS];
        if (j < NMEAS) { cr[j] = Ar[j*MDIM + i]; ci[j] = Ai[j*MDIM + i]; }
        __syncthreads();
        float sr = 0.f, si = 0.f;
        for (int n = 0; n < NMEAS; n++) {
            float arj = Ar[n*MDIM + j], aij = Ai[n*MDIM + j];
            sr += cr[n]*arj + ci[n]*aij;
            si += cr[n]*aij - ci[n]*arj;
        }
        g_AAr[i*MDIM + j] = sr;
        g_AAi[i*MDIM + j] = si;
        if (j == i) g_D[i] = sr;
        if (i == 0 && j == 0) g_max = 0u;
    } else {
        int b0 = (blockIdx.x - 256) * 8;
        int tid = threadIdx.x;
        __shared__ float sYr[8][NMEAS], sYi[8][NMEAS];
        for (int idx = tid; idx < 8*NMEAS; idx += 256) {
            int bl = idx >> 7, n = idx & 127;
            sYr[bl][n] = Yr[(b0 + bl)*NMEAS + n];
            sYi[bl][n] = Yi[(b0 + bl)*NMEAS + n];
        }
        __syncthreads();
        int m = tid;
        float ayr[8], ayi[8];
        #pragma unroll
        for (int q = 0; q < 8; q++) { ayr[q] = 0.f; ayi[q] = 0.f; }
        for (int n = 0; n < NMEAS; n++) {
            float ar = Ar[n*MDIM + m], ai = Ai[n*MDIM + m];
            #pragma unroll
            for (int q = 0; q < 8; q++) {
                float yr = sYr[q][n], yi = sYi[q][n];
                ayr[q] += ar*yr + ai*yi;
                ayi[q] += ar*yi - ai*yr;
            }
        }
        #pragma unroll
        for (int q = 0; q < 8; q++) {
            g_AYr[(b0 + q)*MDIM + m] = ayr[q];
            g_AYi[(b0 + q)*MDIM + m] = ayi[q];
        }
        // ||Y||^2: warp wq reduces batch b0+wq
        int wq = tid >> 5, lane = tid & 31;
        float s = 0.f;
        #pragma unroll
        for (int o = 0; o < 4; o++) {
            float yr = sYr[wq][lane + 32*o], yi = sYi[wq][lane + 32*o];
            s += yr*yr + yi*yi;
        }
        #pragma unroll
        for (int o = 16; o > 0; o >>= 1) s += __shfl_down_sync(0xffffffffu, s, o);
        if (lane == 0) g_Yn[b0 + wq] = s;
    }
}

// ---------------- K2: conv1 (2->32, 3x3) + relu, f32x2 h-pairs -------------
// fill reads g_AYr/g_AYi [b][m]: h-contiguous, t-swept -> coalesced
__global__ __launch_bounds__(256) void k_conv1(const float* __restrict__ w1,
                                               const float* __restrict__ b1) {
    __shared__ float ws[576];
    __shared__ float bs[32];
    __shared__ float2 px[2*34*11];
    int tid = threadIdx.x;
    int w0 = blockIdx.x * 32;
    int hbase = blockIdx.y * 32;
    for (int idx = tid; idx < 576; idx += 256) ws[idx] = w1[idx];
    if (tid < 32) bs[tid] = b1[tid];
    int wl = tid & 31, og = tid >> 5;
    int oc0 = og * 4;
    for (int hc = 0; hc < 2; hc++) {
        int hb = hbase + hc*16;
        __syncthreads();
        for (int idx = tid; idx < 680; idx += 256) {
            int ic = idx / 340, r = idx % 340, wll = r / 10, t = r % 10;
            int h1 = hb - 1 + t, h2 = h1 + 8;
            int w = w0 - 1 + wll;
            bool wok = (w >= 0 && w < BATCH);
            const float* src = ic ? g_AYi : g_AYr;
            const float* row = src + (size_t)w*MDIM;
            float v1 = (wok && h1 >= 0 && h1 < MDIM) ? row[h1] : 0.f;
            float v2 = (wok && h2 < MDIM)            ? row[h2] : 0.f;
            px[(ic*34 + wll)*11 + t] = make_float2(v1, v2);
        }
        __syncthreads();
        ull acc[4][8];
        #pragma unroll
        for (int o = 0; o < 4; o++) {
            ull bp = pk2(bs[oc0 + o], bs[oc0 + o]);
            #pragma unroll
            for (int p = 0; p < 8; p++) acc[o][p] = bp;
        }
        #pragma unroll
        for (int ic = 0; ic < 2; ic++) {
            #pragma unroll
            for (int kw = 0; kw < 3; kw++) {
                const float2* pp = px + (ic*34 + wl + kw)*11;
                ull xp[10];
                #pragma unroll
                for (int t = 0; t < 10; t++) xp[t] = *(const ull*)(pp + t);
                #pragma unroll
                for (int kh = 0; kh < 3; kh++) {
                    ull wp[4];
                    #pragma unroll
                    for (int o = 0; o < 4; o++) {
                        float wv = ws[(oc0 + o)*18 + ic*9 + kh*3 + kw];
                        wp[o] = pk2(wv, wv);
                    }
                    #pragma unroll
                    for (int p = 0; p < 8; p++) {
                        fma2(acc[0][p], wp[0], xp[p + kh]);
                        fma2(acc[1][p], wp[1], xp[p + kh]);
                        fma2(acc[2][p], wp[2], xp[p + kh]);
                        fma2(acc[3][p], wp[3], xp[p + kh]);
                    }
                }
            }
        }
        #pragma unroll
        for (int o = 0; o < 4; o++) {
            int oc = oc0 + o;
            #pragma unroll
            for (int p = 0; p < 8; p++) {
                float2 v = upk2(acc[o][p]);
                g_F1[(oc*MDIM + hb + p)*BATCH + w0 + wl]     = fmaxf(v.x, 0.f);
                g_F1[(oc*MDIM + hb + 8 + p)*BATCH + w0 + wl] = fmaxf(v.y, 0.f);
            }
        }
    }
}

// ---------------- K3: conv2 (R7 verbatim) ----------------------------------
#define CPITCH 11
__global__ __launch_bounds__(256) void k_conv2(const float* __restrict__ w2,
                                               const float* __restrict__ b2) {
    float* wsm = sm2;                          // 9216 floats (32 oc)
    float2* px = (float2*)(sm2 + 9216);        // 32*18*11 float2
    __shared__ float bs[32];
    int tid = threadIdx.x;
    int w0 = blockIdx.x * 16;
    int by = blockIdx.y;
    int oz = blockIdx.z;
    for (int idx = tid; idx < 9216; idx += 256) wsm[idx] = w2[oz*9216 + idx];
    if (tid < 32) bs[tid] = b2[oz*32 + tid];
    int wl = tid & 15, og = tid >> 4;
    int o0 = og, o1 = og + 16;
    float sum2[2] = {0.f, 0.f};
    for (int hc = 0; hc < 8; hc++) {
        int hb = by*128 + hc*16;
        __syncthreads();
        for (int idx = tid; idx < 5760; idx += 256) {
            int ic = idx / 180, r = idx % 180, t = r / 18, wll = r % 18;
            int h1 = hb - 1 + t, h2 = h1 + 8;
            int w = w0 - 1 + wll;
            bool wok = (w >= 0 && w < BATCH);
            const float* base = g_F1 + (size_t)ic*MDIM*BATCH + w;
            float v1 = (wok && h1 >= 0 && h1 < MDIM) ? base[(size_t)h1*BATCH] : 0.f;
            float v2 = (wok && h2 < MDIM)            ? base[(size_t)h2*BATCH] : 0.f;
            px[(ic*18 + wll)*CPITCH + t] = make_float2(v1, v2);
        }
        __syncthreads();
        ull acc[2][8];
        {
            ull b0p = pk2(bs[o0], bs[o0]);
            ull b1p = pk2(bs[o1], bs[o1]);
            #pragma unroll
            for (int p = 0; p < 8; p++) { acc[0][p] = b0p; acc[1][p] = b1p; }
        }
        for (int ic = 0; ic < 32; ic++) {
            const float2* pb = px + (ic*18 + wl)*CPITCH;
            const float* wb = wsm + ic*9;
            #pragma unroll
            for (int kw = 0; kw < 3; kw++) {
                const float2* pp = pb + kw*CPITCH;
                ull xp[10];
                #pragma unroll
                for (int t = 0; t < 10; t++) xp[t] = *(const ull*)(pp + t);
                #pragma unroll
                for (int kh = 0; kh < 3; kh++) {
                    float wv0 = wb[o0*288 + kh*3 + kw];
                    float wv1 = wb[o1*288 + kh*3 + kw];
                    ull wp0 = pk2(wv0, wv0);
                    ull wp1 = pk2(wv1, wv1);
                    #pragma unroll
                    for (int p = 0; p < 8; p++) {
                        fma2(acc[0][p], wp0, xp[p + kh]);
                        fma2(acc[1][p], wp1, xp[p + kh]);
                    }
                }
            }
        }
        #pragma unroll
        for (int o = 0; o < 2; o++)
            #pragma unroll
            for (int p = 0; p < 8; p++) {
                float2 v = upk2(acc[o][p]);
                sum2[o] += fmaxf(v.x, 0.f) + fmaxf(v.y, 0.f);
            }
    }
    g_fmp[(by*64 + oz*32 + o0)*BATCH + w0 + wl] = sum2[0] * (1.f / 256.f);
    g_fmp[(by*64 + oz*32 + o1)*BATCH + w0 + wl] = sum2[1] * (1.f / 256.f);
}

// ---------------- K4: conv1d heads, split across layers (grid.y = 7) -------
__global__ __launch_bounds__(128) void k_heads(
        const float* __restrict__ hcw, const float* __restrict__ hcb,
        const float* __restrict__ hdw, const float* __restrict__ hdb,
        const float* __restrict__ hTw, const float* __restrict__ hTb) {
    float* sf = sm2;              // 64 * 130
    float* sw = sm2 + 64*130;     // 4 * 192
    __shared__ float sb[4];
    int tid = threadIdx.x;
    int b0 = blockIdx.x * 128;
    int l0 = blockIdx.y * 4;
    for (int idx = tid; idx < 64*130; idx += 128) {
        int ic = idx / 130, off = idx % 130;
        int b = b0 - 1 + off;
        float v = 0.f;
        if (b >= 0 && b < BATCH) v = g_fmp[ic*BATCH + b] + g_fmp[(64 + ic)*BATCH + b];
        sf[idx] = v;
    }
    for (int idx = tid; idx < 4*192; idx += 128) {
        int l = l0 + idx / 192, r = idx % 192;
        sw[idx] = (l < 9) ? hcw[l*192 + r] : (l < 18) ? hdw[(l-9)*192 + r] : hTw[(l-18)*192 + r];
    }
    if (tid < 4) {
        int l = l0 + tid;
        sb[tid] = (l < 9) ? hcb[l] : (l < 18) ? hdb[l-9] : hTb[l-18];
    }
    __syncthreads();
    float acc[4];
    #pragma unroll
    for (int q = 0; q < 4; q++) acc[q] = sb[q];
    for (int ic = 0; ic < 64; ic++) {
        float x0 = sf[ic*130 + tid];
        float x1 = sf[ic*130 + tid + 1];
        float x2 = sf[ic*130 + tid + 2];
        #pragma unroll
        for (int q = 0; q < 4; q++) {
            const float* w = sw + q*192 + ic*3;
            acc[q] += w[0]*x0 + w[1]*x1 + w[2]*x2;
        }
    }
    int b = b0 + tid;
    #pragma unroll
    for (int q = 0; q < 4; q++) {
        int l = l0 + q;
        float v = fabsf(acc[q]);
        if (l < 9)       { v = fminf(fmaxf(v, 1e-6f), 100.f); g_c[b*9 + l] = v; }
        else if (l < 18) { v = fmaxf(v, 1e-6f);               g_d[b*9 + (l-9)] = v; }
        else             { v = fminf(fmaxf(v, 1e-6f), 100.f); g_T[b*10 + (l-18)] = v; }
    }
}

// ---------------- K6: W = AA @ U. 64b x 32i tiles, 128 thr, grid (32,8) ----
#define GP 17
__global__ __launch_bounds__(128) void k_mm() {
    __shared__ ull sU2[64*GP], sUs[64*GP], sA2[32*GP];
    int tid = threadIdx.x;
    int b0 = blockIdx.x * 64, i0 = blockIdx.y * 32;
    int tx = tid & 7, ty = tid >> 3;
    int lrU = tid >> 1, lcU = (tid & 1) * 8;
    int lrA = tid >> 2, lcA = (tid & 3) * 4;
    float4 fUr0 = *(const float4*)&g_Ur[(b0 + lrU)*MDIM + lcU];
    float4 fUr1 = *(const float4*)&g_Ur[(b0 + lrU)*MDIM + lcU + 4];
    float4 fUi0 = *(const float4*)&g_Ui[(b0 + lrU)*MDIM + lcU];
    float4 fUi1 = *(const float4*)&g_Ui[(b0 + lrU)*MDIM + lcU + 4];
    float4 fAr  = *(const float4*)&g_AAr[(i0 + lrA)*MDIM + lcA];
    float4 fAi  = *(const float4*)&g_AAi[(i0 + lrA)*MDIM + lcA];
    ull acc[4][4];
    #pragma unroll
    for (int u = 0; u < 4; u++)
        #pragma unroll
        for (int v = 0; v < 4; v++) acc[u][v] = 0ull;
    for (int jc = 0; jc < MDIM; jc += 16) {
        __syncthreads();
        {
            float ur[8] = {fUr0.x, fUr0.y, fUr0.z, fUr0.w, fUr1.x, fUr1.y, fUr1.z, fUr1.w};
            float ui[8] = {fUi0.x, fUi0.y, fUi0.z, fUi0.w, fUi1.x, fUi1.y, fUi1.z, fUi1.w};
            float ar[4] = {fAr.x, fAr.y, fAr.z, fAr.w};
            float ai[4] = {fAi.x, fAi.y, fAi.z, fAi.w};
            #pragma unroll
            for (int t = 0; t < 8; t++) {
                sU2[lrU*GP + lcU + t] = pk2(ur[t], ui[t]);
                sUs[lrU*GP + lcU + t] = pk2(-ui[t], ur[t]);
            }
            #pragma unroll
            for (int t = 0; t < 4; t++)
                sA2[lrA*GP + lcA + t] = pk2(ar[t], ai[t]);
        }
        __syncthreads();
        if (jc + 16 < MDIM) {
            int cU = jc + 16 + lcU, cA = jc + 16 + lcA;
            fUr0 = *(const float4*)&g_Ur[(b0 + lrU)*MDIM + cU];
            fUr1 = *(const float4*)&g_Ur[(b0 + lrU)*MDIM + cU + 4];
            fUi0 = *(const float4*)&g_Ui[(b0 + lrU)*MDIM + cU];
            fUi1 = *(const float4*)&g_Ui[(b0 + lrU)*MDIM + cU + 4];
            fAr  = *(const float4*)&g_AAr[(i0 + lrA)*MDIM + cA];
            fAi  = *(const float4*)&g_AAi[(i0 + lrA)*MDIM + cA];
        }
        #pragma unroll 4
        for (int j = 0; j < 16; j++) {
            ull u2[4], us[4];
            #pragma unroll
            for (int u = 0; u < 4; u++) {
                u2[u] = sU2[(ty + 16*u)*GP + j];
                us[u] = sUs[(ty + 16*u)*GP + j];
            }
            #pragma unroll
            for (int v = 0; v < 4; v++) {
                float2 a = upk2(sA2[(tx + 8*v)*GP + j]);
                ull arr = pk2(a.x, a.x);
                ull aii = pk2(a.y, a.y);
                #pragma unroll
                for (int u = 0; u < 4; u++) {
                    fma2(acc[u][v], arr, u2[u]);
                    fma2(acc[u][v], aii, us[u]);
                }
            }
        }
    }
    #pragma unroll
    for (int u = 0; u < 4; u++) {
        int b = b0 + ty + 16*u;
        #pragma unroll
        for (int v = 0; v < 4; v++) {
            int i = i0 + tx + 8*v;
            float2 cc = upk2(acc[u][v]);
            g_Wr[b*MDIM + i] = cc.x;
            g_Wi[b*MDIM + i] = cc.y;
        }
    }
}

// ---------------- K7: fused update: eps, Sigma, eps2, U (in place), Lam ----
__global__ __launch_bounds__(256) void k_up(int k,
        const float* __restrict__ a0p, const float* __restrict__ b0p,
        float* __restrict__ out) {
    int b = blockIdx.x, i = threadIdx.x;
    __shared__ float sr1[8];
    __shared__ float sEps;
    int lane = i & 31, w = i >> 5;
    float ur = 0.f, ui = 0.f, wr = 0.f, wi = 0.f;
    if (k > 0) {
        ur = g_Ur[b*MDIM + i]; ui = g_Ui[b*MDIM + i];
        wr = g_Wr[b*MDIM + i];
        wi = g_Wi[b*MDIM + i];
    }
    float ayr = g_AYr[b*MDIM + i], ayi = g_AYi[b*MDIM + i];
    float lam;
    if (k > 0) lam = g_Lam[b*MDIM + i];
    else       lam = g_c[b*9] / g_d[b*9];
    float Dm = g_D[i];
    float eps;
    if (k > 0) {
        float loc = ur*wr + ui*wi - 2.f*(ayr*ur + ayi*ui);
        #pragma unroll
        for (int o = 16; o > 0; o >>= 1) loc += __shfl_down_sync(0xffffffffu, loc, o);
        if (lane == 0) sr1[w] = loc;
        __syncthreads();
        if (i == 0) {
            float s = 0.f;
            #pragma unroll
            for (int q = 0; q < 8; q++) s += sr1[q];
            float eps1 = g_Yn[b] + s;
            float a = a0p[0] + (float)NMEAS;
            sEps = a / (b0p[0] + eps1 + g_eps2[b] + 1e-6f);
        }
        __syncthreads();
        eps = sEps;
    } else {
        eps = a0p[0] / b0p[0];
    }
    float sig = 1.f / (eps*Dm + lam + 1e-6f);
    float Tk = g_T[b*10 + k];
    float inv = eps / (eps*Tk + lam + 1e-6f);
    float unr = inv * (Tk*ur - wr + ayr);
    float uni = inv * (Tk*ui - wi + ayi);
    if (k < LNUM - 1) {
        float v = Dm * sig;
        #pragma unroll
        for (int o = 16; o > 0; o >>= 1) v += __shfl_down_sync(0xffffffffu, v, o);
        __syncthreads();
        if (lane == 0) sr1[w] = v;
        __syncthreads();
        if (i == 0) {
            float s = 0.f;
            #pragma unroll
            for (int q = 0; q < 8; q++) s += sr1[q];
            g_eps2[b] = s;
        }
        g_Ur[b*MDIM + i] = unr;
        g_Ui[b*MDIM + i] = uni;
        float ck = g_c[b*9 + k], dk = g_d[b*9 + k];
        g_Lam[b*MDIM + i] = (ck + 1.f) / (dk + unr*unr + uni*uni + sig + 1e-6f);
    } else {
        float v = sqrtf(unr*unr + uni*uni);
        out[b*MDIM + i] = v;
        float mv = v;
        #pragma unroll
        for (int o = 16; o > 0; o >>= 1) mv = fmaxf(mv, __shfl_down_sync(0xffffffffu, mv, o));
        __syncthreads();
        if (lane == 0) sr1[w] = mv;
        __syncthreads();
        if (i == 0) {
            float s = sr1[0];
            #pragma unroll
            for (int q = 1; q < 8; q++) s = fmaxf(s, sr1[q]);
            atomicMax(&g_max, __float_as_uint(s));
        }
    }
}

// ---------------- K10: scale + diagnostic tails ----------------------------
__global__ void k_final(float* __restrict__ out) {
    int bid = blockIdx.x;
    if (bid < BATCH) {
        int idx = bid * 256 + threadIdx.x;
        float mx = __uint_as_float(g_max);
        out[idx] = out[idx] / (mx + 1e-8f);
    } else {
        int t = threadIdx.x;
        int base = BATCH * MDIM;
        if (t < 9)       out[base + t] = g_c[(BATCH - 1)*9 + t];
        else if (t < 18) out[base + t] = g_d[(BATCH - 1)*9 + (t - 9)];
        else if (t < 28) out[base + t] = g_T[(BATCH - 1)*10 + (t - 18)];
    }
}

// ---------------- launch ---------------------------------------------------
extern "C" void kernel_launch(void* const* d_in, const int* in_sizes, int n_in,
                              void* d_out, int out_size) {
    const float* Yr  = (const float*)d_in[0];
    const float* Yi  = (const float*)d_in[1];
    const float* Ar  = (const float*)d_in[2];
    const float* Ai  = (const float*)d_in[3];
    const float* c1w = (const float*)d_in[4];
    const float* c1b = (const float*)d_in[5];
    const float* c2w = (const float*)d_in[6];
    const float* c2b = (const float*)d_in[7];
    const float* hcw = (const float*)d_in[8];
    const float* hcb = (const float*)d_in[9];
    const float* hdw = (const float*)d_in[10];
    const float* hdb = (const float*)d_in[11];
    const float* hTw = (const float*)d_in[12];
    const float* hTb = (const float*)d_in[13];
    const float* a0  = (const float*)d_in[14];
    const float* b0  = (const float*)d_in[15];
    float* out = (float*)d_out;

    int conv2_smem = 9216*4 + 32*18*CPITCH*8;           // 87552
    int heads_smem = (64*130 + 4*192)*4;                // 36352
    cudaFuncSetAttribute(k_conv2, cudaFuncAttributeMaxDynamicSharedMemorySize, conv2_smem);
    cudaFuncSetAttribute(k_heads, cudaFuncAttributeMaxDynamicSharedMemorySize, heads_smem);

    k_front<<<512, 256>>>(Yr, Yi, Ar, Ai);
    k_conv1<<<dim3(64, 8), 256>>>(c1w, c1b);
    k_conv2<<<dim3(128, 2, 2), 256, conv2_smem>>>(c2w, c2b);
    k_heads<<<dim3(16, 7), 128, heads_smem>>>(hcw, hcb, hdw, hdb, hTw, hTb);

    for (int k = 0; k < LNUM; k++) {
        if (k > 0) k_mm<<<dim3(32, 8), 128>>>();
        k_up<<<BATCH, 256>>>(k, a0, b0, out);
    }
    k_final<<<2049, 256>>>(out);
}